// round 14
// baseline (speedup 1.0000x reference)
#include <cuda_runtime.h>
#include <cuda_bf16.h>
#include <cstdint>

#define B_    4
#define C_    64
#define CI_   32
#define N_    4096
#define TQ    64             // queries per CTA
#define TKEY  64             // keys per tile
#define NT_   (N_/TKEY)      // 64 tiles
#define LOG2E 1.44269504088896340736f
#define M0L2  (80.0f * LOG2E)

// gmem scratch (static, no allocs): bf16 hi/lo, PRE-SWIZZLED word layouts
__device__ uint32_t qk_hi[B_ * N_ * (C_ / 2)];   // [b][n][c/2] ^ ((n&7)<<2)
__device__ uint32_t qk_lo[B_ * N_ * (C_ / 2)];
__device__ uint32_t v_hi [B_ * CI_ * (N_ / 2)];  // [b][o][n/2] ^ ((o&7)<<2)
__device__ uint32_t v_lo [B_ * CI_ * (N_ / 2)];

static __device__ __forceinline__ void bsplit(float v, uint16_t& h, uint16_t& l) {
    __nv_bfloat16 hb = __float2bfloat16(v);
    float hf = __bfloat162float(hb);
    __nv_bfloat16 lb = __float2bfloat16(v - hf);
    h = __bfloat16_as_ushort(hb);
    l = __bfloat16_as_ushort(lb);
}
static __device__ __forceinline__ float ex2f(float x) {
    float y; asm("ex2.approx.ftz.f32 %0, %1;" : "=f"(y) : "f"(x)); return y;
}
static __device__ __forceinline__ void mma_bf16(
    float* c, const uint32_t* a, uint32_t b0, uint32_t b1)
{
    asm volatile(
        "mma.sync.aligned.m16n8k16.row.col.f32.bf16.bf16.f32 "
        "{%0,%1,%2,%3},{%4,%5,%6,%7},{%8,%9},{%0,%1,%2,%3};"
        : "+f"(c[0]), "+f"(c[1]), "+f"(c[2]), "+f"(c[3])
        : "r"(a[0]), "r"(a[1]), "r"(a[2]), "r"(a[3]), "r"(b0), "r"(b1));
}
static __device__ __forceinline__ uint32_t smem_u32(const void* p) {
    uint32_t a;
    asm("{ .reg .u64 t; cvta.to.shared.u64 t, %1; cvt.u32.u64 %0, t; }" : "=r"(a) : "l"(p));
    return a;
}
#define LDSM4(r, a) asm volatile( \
    "ldmatrix.sync.aligned.m8n8.x4.shared.b16 {%0,%1,%2,%3}, [%4];" \
    : "=r"((r)[0]), "=r"((r)[1]), "=r"((r)[2]), "=r"((r)[3]) : "r"(a))
#define CPA16(s, g)  asm volatile("cp.async.cg.shared.global [%0], [%1], 16;" :: "r"(s), "l"(g) : "memory")
#define CPA_COMMIT() asm volatile("cp.async.commit_group;" ::: "memory")
#define CPA_WAIT1()  asm volatile("cp.async.wait_group 1;" ::: "memory")
#define CPA_WAIT0()  asm volatile("cp.async.wait_group 0;" ::: "memory")

// ---------------------------------------------------------------------------
// Kernel 1: prep (unchanged).
// ---------------------------------------------------------------------------
__global__ __launch_bounds__(128) void prep_kernel(
    const float* __restrict__ x,
    const float* __restrict__ Wg,
    const float* __restrict__ bg)
{
    __shared__ __align__(16) float sW[CI_ * C_];
    __shared__ float sb[CI_];
    int tid = threadIdx.x;
    for (int i = tid; i < CI_ * C_; i += 128) sW[i] = Wg[i];
    if (tid < CI_) sb[tid] = bg[tid];
    __syncthreads();

    int gid = blockIdx.x * 128 + tid;
    int b = gid >> 12;
    int n = gid & (N_ - 1);
    const float* xp = x + (size_t)b * C_ * N_ + n;

    float xv[C_];
    #pragma unroll
    for (int c = 0; c < C_; c++) xv[c] = xp[c * N_];

    uint32_t rowbase = (uint32_t)gid * (C_ / 2);
    uint32_t msk = (n & 7) << 2;
    #pragma unroll
    for (int w = 0; w < C_ / 2; w++) {
        uint16_t h0, l0, h1, l1;
        bsplit(xv[2 * w + 0], h0, l0);
        bsplit(xv[2 * w + 1], h1, l1);
        qk_hi[rowbase + (w ^ msk)] = (uint32_t)h0 | ((uint32_t)h1 << 16);
        qk_lo[rowbase + (w ^ msk)] = (uint32_t)l0 | ((uint32_t)l1 << 16);
    }

    #pragma unroll
    for (int o = 0; o < CI_; o++) {
        float acc = sb[o];
        #pragma unroll
        for (int c4 = 0; c4 < C_; c4 += 4) {
            float4 w = *(const float4*)(sW + o * C_ + c4);
            acc = fmaf(xv[c4 + 0], w.x, acc);
            acc = fmaf(xv[c4 + 1], w.y, acc);
            acc = fmaf(xv[c4 + 2], w.z, acc);
            acc = fmaf(xv[c4 + 3], w.w, acc);
        }
        uint16_t h, l;
        bsplit(acc, h, l);
        uint32_t widx = (uint32_t)(b * CI_ + o) * (N_ / 2) + ((n >> 1) ^ ((o & 7) << 2));
        uint32_t eidx = widx * 2 + (n & 1);
        ((uint16_t*)v_hi)[eidx] = h;
        ((uint16_t*)v_lo)[eidx] = l;
    }
}

// ---------------------------------------------------------------------------
// Kernel 2: HMMA flash, TQ=64, 8 warps = 2 key-column-groups x 4 m16 warps,
// 2 CTAs/SM. grid = 256 CTAs x 256 threads.
// ---------------------------------------------------------------------------
// smem byte offsets
#define SQH   0u
#define SQL   8192u
#define SLOT0 16384u        // 2 slots, 24576 B each: KH +0, KL +8192, VH +16384, VL +20480
#define SLOTSZ 24576u
#define SWZo  65536u
#define SBZo  73728u
#define SYo   73984u        // 2 groups x 64 q x 32 o floats = 16KB
#define SLo   90368u        // 2 x 64 floats
#define SM_TOTAL 90880u

__global__ __launch_bounds__(256, 2) void flash_mma(
    const float* __restrict__ x,
    const float* __restrict__ Wz,
    const float* __restrict__ bz,
    float* __restrict__ out)
{
    extern __shared__ char smem[];
    uint32_t sb32 = smem_u32(smem);
    int tid = threadIdx.x, wid = tid >> 5, lane = tid & 31;
    int g = lane >> 2, tig = lane & 3;
    int h  = wid >> 2;                 // key-column group: keys [32h, 32h+32)
    int wq = (wid & 3) * 16;           // query rows of this warp (m16)
    int b  = blockIdx.x >> 6;          // N/TQ = 64 CTAs per batch
    int q0 = (blockIdx.x & 63) * TQ;

    const uint4* gQKh = (const uint4*)(qk_hi + (size_t)b * N_ * (C_ / 2));
    const uint4* gQKl = (const uint4*)(qk_lo + (size_t)b * N_ * (C_ / 2));
    const uint4* gVh4 = (const uint4*)v_hi;
    const uint4* gVl4 = (const uint4*)v_lo;
    int bCI = b * CI_;

    // per-thread ldmatrix address components
    uint32_t sw   = (lane & 7) << 2;                  // word-swizzle XOR
    uint32_t r8   = (lane & 7) | ((lane >> 4) << 3);  // row within 16-block (K/V)
    uint32_t m4   = ((lane >> 3) & 1) << 2;           // k-octet word offset (K/V)
    uint32_t qrow = lane & 15;                        // row within 16-block (Q)
    uint32_t qm4  = (lane >> 4) << 2;                 // k-octet word offset (Q)

    // ---- prefetch tile 0 into slot 0 ----
    {
        uint32_t sl = sb32 + SLOT0;
        CPA16(sl + tid * 16,                 gQKh + tid);
        CPA16(sl + (tid + 256) * 16,         gQKh + tid + 256);
        CPA16(sl + 8192u + tid * 16,         gQKl + tid);
        CPA16(sl + 8192u + (tid + 256) * 16, gQKl + tid + 256);
        int o = tid >> 3, part = tid & 7;
        size_t s4 = (size_t)(bCI + o) * (N_ / 8) + part;
        CPA16(sl + 16384u + tid * 16, gVh4 + s4);
        CPA16(sl + 20480u + tid * 16, gVl4 + s4);
        CPA_COMMIT();
    }

    // ---- Q tile + epilogue constants (plain loads, once) ----
    {
        const uint4* gh = gQKh + (size_t)q0 * 8;      // 64 rows x 8 uint4
        const uint4* gl = gQKl + (size_t)q0 * 8;
        uint4* sh = (uint4*)(smem + SQH);
        uint4* sl = (uint4*)(smem + SQL);
        #pragma unroll
        for (int r = 0; r < 2; r++) { int i = r * 256 + tid; sh[i] = gh[i]; sl[i] = gl[i]; }
        for (int i = tid; i < C_ * CI_; i += 256) ((float*)(smem + SWZo))[i] = Wz[i];
        if (tid < C_) ((float*)(smem + SBZo))[tid] = bz[tid];
    }

    float Y[4][4];
    #pragma unroll
    for (int ot = 0; ot < 4; ot++)
        #pragma unroll
        for (int r = 0; r < 4; r++) Y[ot][r] = 0.f;
    float l2[2] = {0.f, 0.f};

    for (int s = 0; s < NT_; s++) {
        // issue next tile, then wait for current
        if (s + 1 < NT_) {
            uint32_t sl = sb32 + SLOT0 + (uint32_t)((s + 1) & 1) * SLOTSZ;
            const uint4* gh = gQKh + (size_t)(s + 1) * 512;
            const uint4* gl = gQKl + (size_t)(s + 1) * 512;
            CPA16(sl + tid * 16,                 gh + tid);
            CPA16(sl + (tid + 256) * 16,         gh + tid + 256);
            CPA16(sl + 8192u + tid * 16,         gl + tid);
            CPA16(sl + 8192u + (tid + 256) * 16, gl + tid + 256);
            int o = tid >> 3, part = tid & 7;
            size_t s4 = (size_t)(bCI + o) * (N_ / 8) + (size_t)(s + 1) * 8 + part;
            CPA16(sl + 16384u + tid * 16, gVh4 + s4);
            CPA16(sl + 20480u + tid * 16, gVl4 + s4);
            CPA_COMMIT();
            CPA_WAIT1();
        } else {
            CPA_WAIT0();
        }
        __syncthreads();

        uint32_t slotb = sb32 + SLOT0 + (uint32_t)(s & 1) * SLOTSZ;

        // ================= QK^T (m16 x n32, keys [32h,32h+32)) =================
        float S[4][4];
        #pragma unroll
        for (int nt = 0; nt < 4; nt++)
            #pragma unroll
            for (int r = 0; r < 4; r++) S[nt][r] = 0.f;

        #pragma unroll
        for (int ks = 0; ks < 4; ks++) {
            uint32_t qw = ((uint32_t)(ks * 8) + qm4) ^ sw;
            uint32_t kw = ((uint32_t)(ks * 8) + m4) ^ sw;
            uint32_t Ah[4], Al[4];
            uint32_t qa = sb32 + SQH + (uint32_t)(wq + qrow) * 128 + qw * 4;
            LDSM4(Ah, qa);
            LDSM4(Al, qa + 8192u);
            #pragma unroll
            for (int ntp = 0; ntp < 2; ntp++) {
                uint32_t ka = slotb + (uint32_t)(h * 32 + ntp * 16 + r8) * 128 + kw * 4;
                uint32_t kh[4], kl[4];
                LDSM4(kh, ka);
                LDSM4(kl, ka + 8192u);
                mma_bf16(S[2 * ntp + 0], Ah, kh[0], kh[1]);
                mma_bf16(S[2 * ntp + 0], Ah, kl[0], kl[1]);
                mma_bf16(S[2 * ntp + 0], Al, kh[0], kh[1]);
                mma_bf16(S[2 * ntp + 1], Ah, kh[2], kh[3]);
                mma_bf16(S[2 * ntp + 1], Ah, kl[2], kl[3]);
                mma_bf16(S[2 * ntp + 1], Al, kh[2], kh[3]);
            }
        }

        // ============ softmax (fixed basis) + PV (keys [32h,32h+32)) ============
        #pragma unroll
        for (int js = 0; js < 2; js++) {
            uint32_t Ph[4], Pl[4];
            #pragma unroll
            for (int half = 0; half < 2; half++) {
                const float* sv = S[2 * js + half];
                #pragma unroll
                for (int rh = 0; rh < 2; rh++) {
                    float p0 = ex2f(fmaf(sv[2 * rh + 0], LOG2E, -M0L2));
                    float p1 = ex2f(fmaf(sv[2 * rh + 1], LOG2E, -M0L2));
                    l2[rh] += p0 + p1;
                    __nv_bfloat162 H = __floats2bfloat162_rn(p0, p1);
                    float h0f = __bfloat162float(H.x);
                    float h1f = __bfloat162float(H.y);
                    __nv_bfloat162 L2v = __floats2bfloat162_rn(p0 - h0f, p1 - h1f);
                    Ph[half * 2 + rh] = *(uint32_t*)&H;
                    Pl[half * 2 + rh] = *(uint32_t*)&L2v;
                }
            }
            uint32_t vw = ((uint32_t)(h * 16 + js * 8) + m4) ^ sw;
            #pragma unroll
            for (int otp = 0; otp < 2; otp++) {
                uint32_t va = slotb + 16384u + (uint32_t)(otp * 16 + r8) * 128 + vw * 4;
                uint32_t vh[4], vl[4];
                LDSM4(vh, va);
                LDSM4(vl, va + 4096u);
                mma_bf16(Y[2 * otp + 0], Ph, vh[0], vh[1]);
                mma_bf16(Y[2 * otp + 0], Ph, vl[0], vl[1]);
                mma_bf16(Y[2 * otp + 0], Pl, vh[0], vh[1]);
                mma_bf16(Y[2 * otp + 1], Ph, vh[2], vh[3]);
                mma_bf16(Y[2 * otp + 1], Ph, vl[2], vl[3]);
                mma_bf16(Y[2 * otp + 1], Pl, vh[2], vh[3]);
            }
        }
        __syncthreads();
    }

    // ---- reduce l across tig; stage group partials ----
    #pragma unroll
    for (int k = 0; k < 2; k++) {
        l2[k] += __shfl_xor_sync(0xffffffffu, l2[k], 1);
        l2[k] += __shfl_xor_sync(0xffffffffu, l2[k], 2);
    }
    float* sY  = (float*)(smem + SYo);
    float* sLp = (float*)(smem + SLo);
    if (tig == 0) {
        sLp[h * 64 + wq + g]     = l2[0];
        sLp[h * 64 + wq + g + 8] = l2[1];
    }
    {
        int r0 = h * 64 + wq + g;
        #pragma unroll
        for (int ot = 0; ot < 4; ot++) {
            int oc = ot * 8 + 2 * tig;
            *(float2*)(sY + (r0)     * 32 + oc) = make_float2(Y[ot][0], Y[ot][1]);
            *(float2*)(sY + (r0 + 8) * 32 + oc) = make_float2(Y[ot][2], Y[ot][3]);
        }
    }
    __syncthreads();

    // ---- epilogue: combine groups; 4 threads per query (16 channels each) ----
    {
        int q  = tid & 63;
        int ch = tid >> 6;                 // 0..3
        float rinv = 1.f / (sLp[q] + sLp[64 + q]);
        float y[CI_];
        #pragma unroll
        for (int o4 = 0; o4 < CI_; o4 += 4) {
            float4 a = *(const float4*)(sY + q * 32 + o4);
            float4 c = *(const float4*)(sY + (64 + q) * 32 + o4);
            y[o4 + 0] = (a.x + c.x) * rinv;
            y[o4 + 1] = (a.y + c.y) * rinv;
            y[o4 + 2] = (a.z + c.z) * rinv;
            y[o4 + 3] = (a.w + c.w) * rinv;
        }

        const float* sWZ = (const float*)(smem + SWZo);
        const float* sBZ = (const float*)(smem + SBZo);
        const float* xb = x + (size_t)b * C_ * N_;
        int qg = q0 + q;
        #pragma unroll
        for (int cc = 0; cc < 16; cc++) {
            int c = ch * 16 + cc;
            float acc = sBZ[c];
            #pragma unroll
            for (int o4 = 0; o4 < CI_; o4 += 4) {
                float4 w = *(const float4*)(sWZ + c * CI_ + o4);
                acc = fmaf(w.x, y[o4 + 0], acc);
                acc = fmaf(w.y, y[o4 + 1], acc);
                acc = fmaf(w.z, y[o4 + 2], acc);
                acc = fmaf(w.w, y[o4 + 3], acc);
            }
            out[((size_t)b * C_ + c) * N_ + qg] = acc + xb[c * N_ + qg];
        }
    }
}

// ---------------------------------------------------------------------------
extern "C" void kernel_launch(void* const* d_in, const int* in_sizes, int n_in,
                              void* d_out, int out_size)
{
    const float* x  = (const float*)d_in[0];
    const float* Wg = (const float*)d_in[1];
    const float* bg = (const float*)d_in[2];
    const float* Wz = (const float*)d_in[3];
    const float* bz = (const float*)d_in[4];
    float* out = (float*)d_out;

    cudaFuncSetAttribute(flash_mma, cudaFuncAttributeMaxDynamicSharedMemorySize, SM_TOTAL);

    prep_kernel<<<(B_ * N_) / 128, 128>>>(x, Wg, bg);
    flash_mma<<<B_ * (N_ / TQ), 256, SM_TOTAL>>>(x, Wz, bz, out);
}

// round 15
// speedup vs baseline: 1.0131x; 1.0131x over previous
#include <cuda_runtime.h>
#include <cuda_bf16.h>
#include <cstdint>

#define B_    4
#define C_    64
#define CI_   32
#define N_    4096
#define TQ    128            // queries per CTA
#define TKEY  64             // keys per tile
#define HT_   32             // tiles per CTA (half of 64)
#define LOG2E 1.44269504088896340736f
#define M0L2  (80.0f * LOG2E)

// gmem scratch (static, no allocs): bf16 hi/lo, PRE-SWIZZLED word layouts
__device__ uint32_t qk_hi[B_ * N_ * (C_ / 2)];   // [b][n][c/2] ^ ((n&7)<<2)
__device__ uint32_t qk_lo[B_ * N_ * (C_ / 2)];
__device__ uint32_t v_hi [B_ * CI_ * (N_ / 2)];  // [b][o][n/2] ^ ((o&7)<<2)
__device__ uint32_t v_lo [B_ * CI_ * (N_ / 2)];
// split-K partials (fixed exponent basis -> plain sum)
__device__ float part_y[B_ * 2 * N_ * CI_];      // [b][half][n][o]
__device__ float part_l[B_ * 2 * N_];            // [b][half][n]

static __device__ __forceinline__ void bsplit(float v, uint16_t& h, uint16_t& l) {
    __nv_bfloat16 hb = __float2bfloat16(v);
    float hf = __bfloat162float(hb);
    __nv_bfloat16 lb = __float2bfloat16(v - hf);
    h = __bfloat16_as_ushort(hb);
    l = __bfloat16_as_ushort(lb);
}
static __device__ __forceinline__ float ex2f(float x) {
    float y; asm("ex2.approx.ftz.f32 %0, %1;" : "=f"(y) : "f"(x)); return y;
}
static __device__ __forceinline__ void mma_bf16(
    float* c, const uint32_t* a, uint32_t b0, uint32_t b1)
{
    asm volatile(
        "mma.sync.aligned.m16n8k16.row.col.f32.bf16.bf16.f32 "
        "{%0,%1,%2,%3},{%4,%5,%6,%7},{%8,%9},{%0,%1,%2,%3};"
        : "+f"(c[0]), "+f"(c[1]), "+f"(c[2]), "+f"(c[3])
        : "r"(a[0]), "r"(a[1]), "r"(a[2]), "r"(a[3]), "r"(b0), "r"(b1));
}
static __device__ __forceinline__ uint32_t smem_u32(const void* p) {
    uint32_t a;
    asm("{ .reg .u64 t; cvta.to.shared.u64 t, %1; cvt.u32.u64 %0, t; }" : "=r"(a) : "l"(p));
    return a;
}
#define LDSM4(r, a) asm volatile( \
    "ldmatrix.sync.aligned.m8n8.x4.shared.b16 {%0,%1,%2,%3}, [%4];" \
    : "=r"((r)[0]), "=r"((r)[1]), "=r"((r)[2]), "=r"((r)[3]) : "r"(a))
#define CPA16(s, g)  asm volatile("cp.async.cg.shared.global [%0], [%1], 16;" :: "r"(s), "l"(g) : "memory")
#define CPA_COMMIT() asm volatile("cp.async.commit_group;" ::: "memory")
#define CPA_WAIT0()  asm volatile("cp.async.wait_group 0;" ::: "memory")

// ---------------------------------------------------------------------------
// Kernel 1: prep (unchanged).
// ---------------------------------------------------------------------------
__global__ __launch_bounds__(128) void prep_kernel(
    const float* __restrict__ x,
    const float* __restrict__ Wg,
    const float* __restrict__ bg)
{
    __shared__ __align__(16) float sW[CI_ * C_];
    __shared__ float sb[CI_];
    int tid = threadIdx.x;
    for (int i = tid; i < CI_ * C_; i += 128) sW[i] = Wg[i];
    if (tid < CI_) sb[tid] = bg[tid];
    __syncthreads();

    int gid = blockIdx.x * 128 + tid;
    int b = gid >> 12;
    int n = gid & (N_ - 1);
    const float* xp = x + (size_t)b * C_ * N_ + n;

    float xv[C_];
    #pragma unroll
    for (int c = 0; c < C_; c++) xv[c] = xp[c * N_];

    uint32_t rowbase = (uint32_t)gid * (C_ / 2);
    uint32_t msk = (n & 7) << 2;
    #pragma unroll
    for (int w = 0; w < C_ / 2; w++) {
        uint16_t h0, l0, h1, l1;
        bsplit(xv[2 * w + 0], h0, l0);
        bsplit(xv[2 * w + 1], h1, l1);
        qk_hi[rowbase + (w ^ msk)] = (uint32_t)h0 | ((uint32_t)h1 << 16);
        qk_lo[rowbase + (w ^ msk)] = (uint32_t)l0 | ((uint32_t)l1 << 16);
    }

    #pragma unroll
    for (int o = 0; o < CI_; o++) {
        float acc = sb[o];
        #pragma unroll
        for (int c4 = 0; c4 < C_; c4 += 4) {
            float4 w = *(const float4*)(sW + o * C_ + c4);
            acc = fmaf(xv[c4 + 0], w.x, acc);
            acc = fmaf(xv[c4 + 1], w.y, acc);
            acc = fmaf(xv[c4 + 2], w.z, acc);
            acc = fmaf(xv[c4 + 3], w.w, acc);
        }
        uint16_t h, l;
        bsplit(acc, h, l);
        uint32_t widx = (uint32_t)(b * CI_ + o) * (N_ / 2) + ((n >> 1) ^ ((o & 7) << 2));
        uint32_t eidx = widx * 2 + (n & 1);
        ((uint16_t*)v_hi)[eidx] = h;
        ((uint16_t*)v_lo)[eidx] = l;
    }
}

// ---------------------------------------------------------------------------
// Kernel 2: HMMA flash, TQ=128, 8 warps x m16, Q frags in registers,
// split-K halves across CTAs. grid = 256 CTAs x 256 threads, 2 CTAs/SM.
// smem: 2 slots x 24576 (KH +0, KL +8192, VH +16384, VL +20480) = 48KB.
// Pre-loop: slot region stages Q (hi 16K, lo 16K). Post-loop: stages Y/l.
// ---------------------------------------------------------------------------
#define SLOTSZ 24576u
#define SM_TOTAL 49152u

__global__ __launch_bounds__(256, 2) void flash_half(const float* __restrict__ dummy)
{
    extern __shared__ char smem[];
    uint32_t sb32 = smem_u32(smem);
    int tid = threadIdx.x, wid = tid >> 5, lane = tid & 31;
    int g = lane >> 2, tig = lane & 3;
    int wq = wid * 16;                  // query rows of this warp (m16)
    int bx = blockIdx.x;
    int b    = bx >> 6;
    int q0   = ((bx >> 1) & 31) * TQ;
    int half = bx & 1;
    int kt0  = half * HT_;

    const uint4* gQKh = (const uint4*)(qk_hi + (size_t)b * N_ * (C_ / 2));
    const uint4* gQKl = (const uint4*)(qk_lo + (size_t)b * N_ * (C_ / 2));
    const uint4* gVh4 = (const uint4*)v_hi;
    const uint4* gVl4 = (const uint4*)v_lo;
    int bCI = b * CI_;

    // per-thread ldmatrix address components
    uint32_t sw   = (lane & 7) << 2;
    uint32_t r8   = (lane & 7) | ((lane >> 4) << 3);
    uint32_t m4   = ((lane >> 3) & 1) << 2;
    uint32_t qrow = lane & 15;
    uint32_t qm4  = (lane >> 4) << 2;

    // ---- stage Q in slot region, LDSM fragments to registers ----
    uint32_t Qh[4][4], Ql[4][4];
    {
        const uint4* gh = gQKh + (size_t)q0 * 8;     // 128 rows x 8 uint4
        const uint4* gl = gQKl + (size_t)q0 * 8;
        uint4* sh = (uint4*)(smem);
        uint4* sl = (uint4*)(smem + 16384u);
        #pragma unroll
        for (int r = 0; r < 4; r++) { int i = r * 256 + tid; sh[i] = gh[i]; sl[i] = gl[i]; }
        __syncthreads();
        #pragma unroll
        for (int ks = 0; ks < 4; ks++) {
            uint32_t qa = sb32 + (uint32_t)(wq + qrow) * 128
                        + ((((uint32_t)(ks * 8)) + qm4) ^ sw) * 4;
            LDSM4(Qh[ks], qa);
            LDSM4(Ql[ks], qa + 16384u);
        }
        __syncthreads();   // Q reads done before cp.async overwrites slots
    }

    // ---- prefetch tile kt0 into slot 0 ----
    {
        uint32_t sl = sb32;
        const uint4* gh = gQKh + (size_t)kt0 * 512;
        const uint4* gl = gQKl + (size_t)kt0 * 512;
        CPA16(sl + tid * 16,                 gh + tid);
        CPA16(sl + (tid + 256) * 16,         gh + tid + 256);
        CPA16(sl + 8192u + tid * 16,         gl + tid);
        CPA16(sl + 8192u + (tid + 256) * 16, gl + tid + 256);
        int o = tid >> 3, part = tid & 7;
        size_t s4 = (size_t)(bCI + o) * (N_ / 8) + (size_t)kt0 * 8 + part;
        CPA16(sl + 16384u + tid * 16, gVh4 + s4);
        CPA16(sl + 20480u + tid * 16, gVl4 + s4);
        CPA_COMMIT();
    }

    float Y[4][4];
    #pragma unroll
    for (int ot = 0; ot < 4; ot++)
        #pragma unroll
        for (int r = 0; r < 4; r++) Y[ot][r] = 0.f;
    float l2[2] = {0.f, 0.f};

    for (int s = 0; s < HT_; s++) {
        CPA_WAIT0();           // tile s resident (issued one full compute ago)
        __syncthreads();       // everyone done with slot of s-1

        // issue cp.async for tile s+1 into slot of s-1 (now free)
        if (s + 1 < HT_) {
            int kt = kt0 + s + 1;
            uint32_t sl = sb32 + (uint32_t)((s + 1) & 1) * SLOTSZ;
            const uint4* gh = gQKh + (size_t)kt * 512;
            const uint4* gl = gQKl + (size_t)kt * 512;
            CPA16(sl + tid * 16,                 gh + tid);
            CPA16(sl + (tid + 256) * 16,         gh + tid + 256);
            CPA16(sl + 8192u + tid * 16,         gl + tid);
            CPA16(sl + 8192u + (tid + 256) * 16, gl + tid + 256);
            int o = tid >> 3, part = tid & 7;
            size_t s4 = (size_t)(bCI + o) * (N_ / 8) + (size_t)kt * 8 + part;
            CPA16(sl + 16384u + tid * 16, gVh4 + s4);
            CPA16(sl + 20480u + tid * 16, gVl4 + s4);
            CPA_COMMIT();
        }

        uint32_t slotb = sb32 + (uint32_t)(s & 1) * SLOTSZ;

        // ================= QK^T (m16 x n64) =================
        float S[8][4];
        #pragma unroll
        for (int nt = 0; nt < 8; nt++)
            #pragma unroll
            for (int r = 0; r < 4; r++) S[nt][r] = 0.f;

        #pragma unroll
        for (int ks = 0; ks < 4; ks++) {
            uint32_t kw = ((uint32_t)(ks * 8) + m4) ^ sw;
            #pragma unroll
            for (int ntp = 0; ntp < 4; ntp++) {
                uint32_t ka = slotb + (uint32_t)(ntp * 16 + r8) * 128 + kw * 4;
                uint32_t kh[4], kl[4];
                LDSM4(kh, ka);
                LDSM4(kl, ka + 8192u);
                mma_bf16(S[2 * ntp + 0], Qh[ks], kh[0], kh[1]);
                mma_bf16(S[2 * ntp + 0], Qh[ks], kl[0], kl[1]);
                mma_bf16(S[2 * ntp + 0], Ql[ks], kh[0], kh[1]);
                mma_bf16(S[2 * ntp + 1], Qh[ks], kh[2], kh[3]);
                mma_bf16(S[2 * ntp + 1], Qh[ks], kl[2], kl[3]);
                mma_bf16(S[2 * ntp + 1], Ql[ks], kh[2], kh[3]);
            }
        }

        // ============ softmax (fixed basis) + PV ============
        #pragma unroll
        for (int js = 0; js < 4; js++) {
            uint32_t Ph[4], Pl[4];
            #pragma unroll
            for (int halfn = 0; halfn < 2; halfn++) {
                const float* sv = S[2 * js + halfn];
                #pragma unroll
                for (int rh = 0; rh < 2; rh++) {
                    float p0 = ex2f(fmaf(sv[2 * rh + 0], LOG2E, -M0L2));
                    float p1 = ex2f(fmaf(sv[2 * rh + 1], LOG2E, -M0L2));
                    l2[rh] += p0 + p1;
                    __nv_bfloat162 H = __floats2bfloat162_rn(p0, p1);
                    float h0f = __bfloat162float(H.x);
                    float h1f = __bfloat162float(H.y);
                    __nv_bfloat162 L2v = __floats2bfloat162_rn(p0 - h0f, p1 - h1f);
                    Ph[halfn * 2 + rh] = *(uint32_t*)&H;
                    Pl[halfn * 2 + rh] = *(uint32_t*)&L2v;
                }
            }
            uint32_t vw = ((uint32_t)(js * 8) + m4) ^ sw;
            #pragma unroll
            for (int otp = 0; otp < 2; otp++) {
                uint32_t va = slotb + 16384u + (uint32_t)(otp * 16 + r8) * 128 + vw * 4;
                uint32_t vh[4], vl[4];
                LDSM4(vh, va);
                LDSM4(vl, va + 4096u);
                mma_bf16(Y[2 * otp + 0], Ph, vh[0], vh[1]);
                mma_bf16(Y[2 * otp + 0], Ph, vl[0], vl[1]);
                mma_bf16(Y[2 * otp + 0], Pl, vh[0], vh[1]);
                mma_bf16(Y[2 * otp + 1], Ph, vh[2], vh[3]);
                mma_bf16(Y[2 * otp + 1], Ph, vl[2], vl[3]);
                mma_bf16(Y[2 * otp + 1], Pl, vh[2], vh[3]);
            }
        }
    }

    // ---- reduce l across tig; stage Y/l in slot region; write partials ----
    #pragma unroll
    for (int k = 0; k < 2; k++) {
        l2[k] += __shfl_xor_sync(0xffffffffu, l2[k], 1);
        l2[k] += __shfl_xor_sync(0xffffffffu, l2[k], 2);
    }
    __syncthreads();                      // all done reading slots
    float* sY  = (float*)(smem);          // 128 x 32 floats = 16KB
    float* sLp = (float*)(smem + 16384u); // 128 floats
    if (tig == 0) {
        sLp[wq + g]     = l2[0];
        sLp[wq + g + 8] = l2[1];
    }
    {
        int r0 = wq + g;
        #pragma unroll
        for (int ot = 0; ot < 4; ot++) {
            int oc = ot * 8 + 2 * tig;
            *(float2*)(sY + (r0)     * 32 + oc) = make_float2(Y[ot][0], Y[ot][1]);
            *(float2*)(sY + (r0 + 8) * 32 + oc) = make_float2(Y[ot][2], Y[ot][3]);
        }
    }
    __syncthreads();

    // partial y: contiguous 4096 floats; partial l: 128 floats
    {
        size_t ybase = ((size_t)(b * 2 + half) * N_ + q0) * CI_;
        float4* gy = (float4*)(part_y + ybase);
        const float4* sy4 = (const float4*)sY;
        #pragma unroll
        for (int r = 0; r < 4; r++) gy[r * 256 + tid] = sy4[r * 256 + tid];
        if (tid < TQ) part_l[(size_t)(b * 2 + half) * N_ + q0 + tid] = sLp[tid];
    }
}

// ---------------------------------------------------------------------------
// Kernel 3: combine halves + Wz projection + bias + residual.
// ---------------------------------------------------------------------------
__global__ __launch_bounds__(128) void combine_kernel(
    const float* __restrict__ x,
    const float* __restrict__ Wz,
    const float* __restrict__ bz,
    float* __restrict__ out)
{
    __shared__ __align__(16) float sW[C_ * CI_];
    __shared__ float sb[C_];
    int tid = threadIdx.x;
    for (int i = tid; i < C_ * CI_; i += 128) sW[i] = Wz[i];
    if (tid < C_) sb[tid] = bz[tid];
    __syncthreads();

    int gid = blockIdx.x * 128 + tid;     // (b, n)
    int b = gid >> 12;
    int n = gid & (N_ - 1);

    float l = part_l[(size_t)(b * 2 + 0) * N_ + n] + part_l[(size_t)(b * 2 + 1) * N_ + n];
    float rinv = 1.f / l;

    const float4* y0 = (const float4*)(part_y + ((size_t)(b * 2 + 0) * N_ + n) * CI_);
    const float4* y1 = (const float4*)(part_y + ((size_t)(b * 2 + 1) * N_ + n) * CI_);
    float y[CI_];
    #pragma unroll
    for (int o4 = 0; o4 < CI_ / 4; o4++) {
        float4 a = y0[o4], c = y1[o4];
        y[4 * o4 + 0] = (a.x + c.x) * rinv;
        y[4 * o4 + 1] = (a.y + c.y) * rinv;
        y[4 * o4 + 2] = (a.z + c.z) * rinv;
        y[4 * o4 + 3] = (a.w + c.w) * rinv;
    }

    const float* xb = x + (size_t)b * C_ * N_;
    float* ob = out + (size_t)b * C_ * N_;
    #pragma unroll
    for (int c = 0; c < C_; c++) {
        float acc = sb[c];
        #pragma unroll
        for (int o4 = 0; o4 < CI_; o4 += 4) {
            float4 w = *(const float4*)(sW + c * CI_ + o4);
            acc = fmaf(w.x, y[o4 + 0], acc);
            acc = fmaf(w.y, y[o4 + 1], acc);
            acc = fmaf(w.z, y[o4 + 2], acc);
            acc = fmaf(w.w, y[o4 + 3], acc);
        }
        ob[c * N_ + n] = acc + xb[c * N_ + n];     // coalesced
    }
}

// ---------------------------------------------------------------------------
extern "C" void kernel_launch(void* const* d_in, const int* in_sizes, int n_in,
                              void* d_out, int out_size)
{
    const float* x  = (const float*)d_in[0];
    const float* Wg = (const float*)d_in[1];
    const float* bg = (const float*)d_in[2];
    const float* Wz = (const float*)d_in[3];
    const float* bz = (const float*)d_in[4];
    float* out = (float*)d_out;

    cudaFuncSetAttribute(flash_half, cudaFuncAttributeMaxDynamicSharedMemorySize, SM_TOTAL);

    prep_kernel<<<(B_ * N_) / 128, 128>>>(x, Wg, bg);
    flash_half<<<B_ * 32 * 2, 256, SM_TOTAL>>>(x);
    combine_kernel<<<(B_ * N_) / 128, 128>>>(x, Wz, bz, out);
}

// round 16
// speedup vs baseline: 1.0328x; 1.0195x over previous
#include <cuda_runtime.h>
#include <cuda_bf16.h>
#include <cstdint>

#define B_    4
#define C_    64
#define CI_   32
#define N_    4096
#define TQ    128            // queries per CTA
#define TKEY  64             // keys per tile
#define NPAIR 32             // pair-steps: groups 0/1 take tiles 2s / 2s+1
#define LOG2E 1.44269504088896340736f
#define M0L2  (80.0f * LOG2E)

// gmem scratch (static, no allocs): bf16 hi/lo, PRE-SWIZZLED word layouts
__device__ uint32_t qk_hi[B_ * N_ * (C_ / 2)];   // [b][n][c/2] ^ ((n&7)<<2)
__device__ uint32_t qk_lo[B_ * N_ * (C_ / 2)];
__device__ uint32_t v_hi [B_ * CI_ * (N_ / 2)];  // [b][o][n/2] ^ ((o&7)<<2)
__device__ uint32_t v_lo [B_ * CI_ * (N_ / 2)];

static __device__ __forceinline__ void bsplit(float v, uint16_t& h, uint16_t& l) {
    __nv_bfloat16 hb = __float2bfloat16(v);
    float hf = __bfloat162float(hb);
    __nv_bfloat16 lb = __float2bfloat16(v - hf);
    h = __bfloat16_as_ushort(hb);
    l = __bfloat16_as_ushort(lb);
}
static __device__ __forceinline__ float ex2f(float x) {
    float y; asm("ex2.approx.ftz.f32 %0, %1;" : "=f"(y) : "f"(x)); return y;
}
static __device__ __forceinline__ void mma_bf16(
    float* c, const uint32_t* a, uint32_t b0, uint32_t b1)
{
    asm volatile(
        "mma.sync.aligned.m16n8k16.row.col.f32.bf16.bf16.f32 "
        "{%0,%1,%2,%3},{%4,%5,%6,%7},{%8,%9},{%0,%1,%2,%3};"
        : "+f"(c[0]), "+f"(c[1]), "+f"(c[2]), "+f"(c[3])
        : "r"(a[0]), "r"(a[1]), "r"(a[2]), "r"(a[3]), "r"(b0), "r"(b1));
}
static __device__ __forceinline__ uint32_t smem_u32(const void* p) {
    uint32_t a;
    asm("{ .reg .u64 t; cvta.to.shared.u64 t, %1; cvt.u32.u64 %0, t; }" : "=r"(a) : "l"(p));
    return a;
}
#define LDSM4(r, a) asm volatile( \
    "ldmatrix.sync.aligned.m8n8.x4.shared.b16 {%0,%1,%2,%3}, [%4];" \
    : "=r"((r)[0]), "=r"((r)[1]), "=r"((r)[2]), "=r"((r)[3]) : "r"(a))
#define CPA16(s, g)  asm volatile("cp.async.cg.shared.global [%0], [%1], 16;" :: "r"(s), "l"(g) : "memory")
#define CPA_COMMIT() asm volatile("cp.async.commit_group;" ::: "memory")
#define CPA_WAIT1()  asm volatile("cp.async.wait_group 1;" ::: "memory")
#define CPA_WAIT0()  asm volatile("cp.async.wait_group 0;" ::: "memory")

// ---------------------------------------------------------------------------
// Kernel 1: prep, 4-way output split for MLP/occupancy. 512 blocks x 128.
// ---------------------------------------------------------------------------
__global__ __launch_bounds__(128) void prep_kernel(
    const float* __restrict__ x,
    const float* __restrict__ Wg,
    const float* __restrict__ bg)
{
    __shared__ __align__(16) float sW[CI_ * C_];
    __shared__ float sb[CI_];
    int tid = threadIdx.x;
    for (int i = tid; i < CI_ * C_; i += 128) sW[i] = Wg[i];
    if (tid < CI_) sb[tid] = bg[tid];
    __syncthreads();

    int gid = blockIdx.x * 128 + tid;          // 0 .. 4*B*N-1
    int quarter = gid >> 14;                   // uniform per block
    int idx = gid & (B_ * N_ - 1);
    int b = idx >> 12;
    int n = idx & (N_ - 1);
    const float* xp = x + (size_t)b * C_ * N_ + n;

    float xv[C_];
    #pragma unroll
    for (int c = 0; c < C_; c++) xv[c] = xp[c * N_];

    if (quarter == 0) {
        uint32_t rowbase = (uint32_t)idx * (C_ / 2);
        uint32_t msk = (n & 7) << 2;
        #pragma unroll
        for (int w = 0; w < C_ / 2; w++) {
            uint16_t h0, l0, h1, l1;
            bsplit(xv[2 * w + 0], h0, l0);
            bsplit(xv[2 * w + 1], h1, l1);
            qk_hi[rowbase + (w ^ msk)] = (uint32_t)h0 | ((uint32_t)h1 << 16);
            qk_lo[rowbase + (w ^ msk)] = (uint32_t)l0 | ((uint32_t)l1 << 16);
        }
    }

    int o0 = quarter * (CI_ / 4);
    #pragma unroll
    for (int o = 0; o < CI_ / 4; o++) {
        int oo = o0 + o;
        float acc = sb[oo];
        #pragma unroll
        for (int c4 = 0; c4 < C_; c4 += 4) {
            float4 w = *(const float4*)(sW + oo * C_ + c4);
            acc = fmaf(xv[c4 + 0], w.x, acc);
            acc = fmaf(xv[c4 + 1], w.y, acc);
            acc = fmaf(xv[c4 + 2], w.z, acc);
            acc = fmaf(xv[c4 + 3], w.w, acc);
        }
        uint16_t h, l;
        bsplit(acc, h, l);
        uint32_t widx = (uint32_t)(b * CI_ + oo) * (N_ / 2) + ((n >> 1) ^ ((oo & 7) << 2));
        uint32_t eidx = widx * 2 + (n & 1);
        ((uint16_t*)v_hi)[eidx] = h;
        ((uint16_t*)v_lo)[eidx] = l;
    }
}

// ---------------------------------------------------------------------------
// Kernel 2: HMMA flash, 512 threads = 2 key-groups x 8 m16 query-warps,
// Q frags in registers, 4 double-buffered slots, fused epilogue.
// grid = 128 CTAs x 512 threads, 1 CTA/SM.
// ---------------------------------------------------------------------------
#define SLOTSZ 24576u        // KH +0, KL +8192, VH +16384, VL +20480
#define SWZo   98304u
#define SBZo   106496u
#define SLo    106752u       // 256 floats
#define SM_TOTAL 107776u

__global__ __launch_bounds__(512, 1) void flash_mma(
    const float* __restrict__ x,
    const float* __restrict__ Wz,
    const float* __restrict__ bz,
    float* __restrict__ out)
{
    extern __shared__ char smem[];
    uint32_t sb32 = smem_u32(smem);
    int tid = threadIdx.x, wid = tid >> 5, lane = tid & 31;
    int g = lane >> 2, tig = lane & 3;
    int h  = wid >> 3;                  // key group: tiles 2s+h
    int wq = (wid & 7) * 16;            // query rows (m16)
    int b  = blockIdx.x >> 5;
    int q0 = (blockIdx.x & 31) * TQ;

    const uint4* gQKh = (const uint4*)(qk_hi + (size_t)b * N_ * (C_ / 2));
    const uint4* gQKl = (const uint4*)(qk_lo + (size_t)b * N_ * (C_ / 2));
    const uint4* gVh4 = (const uint4*)v_hi;
    const uint4* gVl4 = (const uint4*)v_lo;
    int bCI = b * CI_;

    // per-thread ldmatrix address components
    uint32_t sw   = (lane & 7) << 2;
    uint32_t r8   = (lane & 7) | ((lane >> 4) << 3);
    uint32_t m4   = ((lane >> 3) & 1) << 2;
    uint32_t qrow = lane & 15;
    uint32_t qm4  = (lane >> 4) << 2;

    // ---- epilogue constants ----
    for (int i = tid; i < C_ * CI_; i += 512) ((float*)(smem + SWZo))[i] = Wz[i];
    if (tid < C_) ((float*)(smem + SBZo))[tid] = bz[tid];

    // ---- stage Q in slot region (first 32KB), LDSM frags to registers ----
    uint32_t Qh[4][4], Ql[4][4];
    {
        const uint4* gh = gQKh + (size_t)q0 * 8;     // 128 rows x 8 uint4
        const uint4* gl = gQKl + (size_t)q0 * 8;
        uint4* sh = (uint4*)(smem);
        uint4* sl = (uint4*)(smem + 16384u);
        #pragma unroll
        for (int r = 0; r < 2; r++) { int i = r * 512 + tid; sh[i] = gh[i]; sl[i] = gl[i]; }
        __syncthreads();
        #pragma unroll
        for (int ks = 0; ks < 4; ks++) {
            uint32_t qa = sb32 + (uint32_t)(wq + qrow) * 128
                        + ((((uint32_t)(ks * 8)) + qm4) ^ sw) * 4;
            LDSM4(Qh[ks], qa);
            LDSM4(Ql[ks], qa + 16384u);
        }
        __syncthreads();   // Q reads done before cp.async overwrites slots
    }

    // ---- prefetch pair 0 (tiles 0,1 -> slots 0,1) ----
    {
        #pragma unroll
        for (int hh = 0; hh < 2; hh++) {
            uint32_t sl = sb32 + (uint32_t)hh * SLOTSZ;
            const uint4* gh = gQKh + (size_t)hh * 512;
            const uint4* gl = gQKl + (size_t)hh * 512;
            CPA16(sl + tid * 16,          gh + tid);
            CPA16(sl + 8192u + tid * 16,  gl + tid);
            if (tid < 128) {
                int o = tid >> 2, part = tid & 3;
                size_t s4 = (size_t)(bCI + o) * (N_ / 8) + (size_t)hh * 8 + part * 2;
                CPA16(sl + 16384u + tid * 32,       gVh4 + s4);
                CPA16(sl + 16384u + tid * 32 + 16,  gVh4 + s4 + 1);
                CPA16(sl + 20480u + tid * 32,       gVl4 + s4);
                CPA16(sl + 20480u + tid * 32 + 16,  gVl4 + s4 + 1);
            }
        }
        CPA_COMMIT();
    }

    float Y[4][4];
    #pragma unroll
    for (int ot = 0; ot < 4; ot++)
        #pragma unroll
        for (int r = 0; r < 4; r++) Y[ot][r] = 0.f;
    float l2[2] = {0.f, 0.f};

    for (int s = 0; s < NPAIR; s++) {
        if (s + 1 < NPAIR) {
            #pragma unroll
            for (int hh = 0; hh < 2; hh++) {
                int kt = 2 * (s + 1) + hh;
                uint32_t sl = sb32 + (uint32_t)(((s + 1) & 1) * 2 + hh) * SLOTSZ;
                const uint4* gh = gQKh + (size_t)kt * 512;
                const uint4* gl = gQKl + (size_t)kt * 512;
                CPA16(sl + tid * 16,          gh + tid);
                CPA16(sl + 8192u + tid * 16,  gl + tid);
                if (tid < 128) {
                    int o = tid >> 2, part = tid & 3;
                    size_t s4 = (size_t)(bCI + o) * (N_ / 8) + (size_t)kt * 8 + part * 2;
                    CPA16(sl + 16384u + tid * 32,       gVh4 + s4);
                    CPA16(sl + 16384u + tid * 32 + 16,  gVh4 + s4 + 1);
                    CPA16(sl + 20480u + tid * 32,       gVl4 + s4);
                    CPA16(sl + 20480u + tid * 32 + 16,  gVl4 + s4 + 1);
                }
            }
            CPA_COMMIT();
            CPA_WAIT1();
        } else {
            CPA_WAIT0();
        }
        __syncthreads();

        uint32_t slotb = sb32 + (uint32_t)((s & 1) * 2 + h) * SLOTSZ;

        // ================= QK^T (m16 x n64) =================
        float S[8][4];
        #pragma unroll
        for (int nt = 0; nt < 8; nt++)
            #pragma unroll
            for (int r = 0; r < 4; r++) S[nt][r] = 0.f;

        #pragma unroll
        for (int ks = 0; ks < 4; ks++) {
            uint32_t kw = ((uint32_t)(ks * 8) + m4) ^ sw;
            #pragma unroll
            for (int ntp = 0; ntp < 4; ntp++) {
                uint32_t ka = slotb + (uint32_t)(ntp * 16 + r8) * 128 + kw * 4;
                uint32_t kh[4], kl[4];
                LDSM4(kh, ka);
                LDSM4(kl, ka + 8192u);
                mma_bf16(S[2 * ntp + 0], Qh[ks], kh[0], kh[1]);
                mma_bf16(S[2 * ntp + 0], Qh[ks], kl[0], kl[1]);
                mma_bf16(S[2 * ntp + 0], Ql[ks], kh[0], kh[1]);
                mma_bf16(S[2 * ntp + 1], Qh[ks], kh[2], kh[3]);
                mma_bf16(S[2 * ntp + 1], Qh[ks], kl[2], kl[3]);
                mma_bf16(S[2 * ntp + 1], Ql[ks], kh[2], kh[3]);
            }
        }

        // ============ softmax (fixed basis) + PV ============
        #pragma unroll
        for (int js = 0; js < 4; js++) {
            uint32_t Ph[4], Pl[4];
            #pragma unroll
            for (int hn = 0; hn < 2; hn++) {
                const float* sv = S[2 * js + hn];
                #pragma unroll
                for (int rh = 0; rh < 2; rh++) {
                    float p0 = ex2f(fmaf(sv[2 * rh + 0], LOG2E, -M0L2));
                    float p1 = ex2f(fmaf(sv[2 * rh + 1], LOG2E, -M0L2));
                    l2[rh] += p0 + p1;
                    __nv_bfloat162 H = __floats2bfloat162_rn(p0, p1);
                    float h0f = __bfloat162float(H.x);
                    float h1f = __bfloat162float(H.y);
                    __nv_bfloat162 L2v = __floats2bfloat162_rn(p0 - h0f, p1 - h1f);
                    Ph[hn * 2 + rh] = *(uint32_t*)&H;
                    Pl[hn * 2 + rh] = *(uint32_t*)&L2v;
                }
            }
            uint32_t vw = ((uint32_t)(js * 8) + m4) ^ sw;
            #pragma unroll
            for (int otp = 0; otp < 2; otp++) {
                uint32_t va = slotb + 16384u + (uint32_t)(otp * 16 + r8) * 128 + vw * 4;
                uint32_t vh[4], vl[4];
                LDSM4(vh, va);
                LDSM4(vl, va + 4096u);
                mma_bf16(Y[2 * otp + 0], Ph, vh[0], vh[1]);
                mma_bf16(Y[2 * otp + 0], Ph, vl[0], vl[1]);
                mma_bf16(Y[2 * otp + 0], Pl, vh[0], vh[1]);
                mma_bf16(Y[2 * otp + 1], Ph, vh[2], vh[3]);
                mma_bf16(Y[2 * otp + 1], Ph, vl[2], vl[3]);
                mma_bf16(Y[2 * otp + 1], Pl, vh[2], vh[3]);
            }
        }
        __syncthreads();
    }

    // ---- reduce l across tig; stage group partials in slot region ----
    #pragma unroll
    for (int k = 0; k < 2; k++) {
        l2[k] += __shfl_xor_sync(0xffffffffu, l2[k], 1);
        l2[k] += __shfl_xor_sync(0xffffffffu, l2[k], 2);
    }
    __syncthreads();                     // all slot reads done
    float* sY  = (float*)(smem);         // 2 groups x 128q x 32o = 32KB
    float* sLp = (float*)(smem + SLo);
    if (tig == 0) {
        sLp[h * 128 + wq + g]     = l2[0];
        sLp[h * 128 + wq + g + 8] = l2[1];
    }
    {
        int r0 = h * 128 + wq + g;
        #pragma unroll
        for (int ot = 0; ot < 4; ot++) {
            int oc = ot * 8 + 2 * tig;
            *(float2*)(sY + (r0)     * 32 + oc) = make_float2(Y[ot][0], Y[ot][1]);
            *(float2*)(sY + (r0 + 8) * 32 + oc) = make_float2(Y[ot][2], Y[ot][3]);
        }
    }
    __syncthreads();

    // ---- epilogue: combine groups; 4 threads per query (16 channels) ----
    {
        int q  = tid & 127;
        int ch = tid >> 7;               // 0..3
        float rinv = 1.f / (sLp[q] + sLp[128 + q]);
        float y[CI_];
        #pragma unroll
        for (int o4 = 0; o4 < CI_; o4 += 4) {
            float4 a = *(const float4*)(sY + q * 32 + o4);
            float4 c = *(const float4*)(sY + (128 + q) * 32 + o4);
            y[o4 + 0] = (a.x + c.x) * rinv;
            y[o4 + 1] = (a.y + c.y) * rinv;
            y[o4 + 2] = (a.z + c.z) * rinv;
            y[o4 + 3] = (a.w + c.w) * rinv;
        }

        const float* sWZ = (const float*)(smem + SWZo);
        const float* sBZ = (const float*)(smem + SBZo);
        const float* xb = x + (size_t)b * C_ * N_;
        int qg = q0 + q;
        #pragma unroll
        for (int cc = 0; cc < 16; cc++) {
            int c = ch * 16 + cc;
            float acc = sBZ[c];
            #pragma unroll
            for (int o4 = 0; o4 < CI_; o4 += 4) {
                float4 w = *(const float4*)(sWZ + c * CI_ + o4);
                acc = fmaf(w.x, y[o4 + 0], acc);
                acc = fmaf(w.y, y[o4 + 1], acc);
                acc = fmaf(w.z, y[o4 + 2], acc);
                acc = fmaf(w.w, y[o4 + 3], acc);
            }
            out[((size_t)b * C_ + c) * N_ + qg] = acc + xb[c * N_ + qg];
        }
    }
}

// ---------------------------------------------------------------------------
extern "C" void kernel_launch(void* const* d_in, const int* in_sizes, int n_in,
                              void* d_out, int out_size)
{
    const float* x  = (const float*)d_in[0];
    const float* Wg = (const float*)d_in[1];
    const float* bg = (const float*)d_in[2];
    const float* Wz = (const float*)d_in[3];
    const float* bz = (const float*)d_in[4];
    float* out = (float*)d_out;

    cudaFuncSetAttribute(flash_mma, cudaFuncAttributeMaxDynamicSharedMemorySize, SM_TOTAL);

    prep_kernel<<<(4 * B_ * N_) / 128, 128>>>(x, Wg, bg);
    flash_mma<<<B_ * (N_ / TQ), 512, SM_TOTAL>>>(x, Wz, bz, out);
}

// round 17
// speedup vs baseline: 1.2055x; 1.1672x over previous
#include <cuda_runtime.h>
#include <cuda_bf16.h>
#include <cuda_fp16.h>
#include <cstdint>

#define B_    4
#define C_    64
#define CI_   32
#define N_    4096
#define TQ    128            // queries per CTA
#define TKEY  64             // keys per tile
#define NPAIR 32             // pair-steps: groups 0/1 take tiles 2s+h
#define LOG2E 1.44269504088896340736f
#define M0L2  (80.0f * LOG2E)

// gmem scratch (static): Q/K fp16 hi/lo, V bf16 hi/lo, PRE-SWIZZLED
__device__ uint32_t qk_hi[B_ * N_ * (C_ / 2)];   // [b][n][c/2] ^ ((n&7)<<2)
__device__ uint32_t qk_lo[B_ * N_ * (C_ / 2)];
__device__ uint32_t v_hi [B_ * CI_ * (N_ / 2)];  // [b][o][n/2] ^ ((o&7)<<2)
__device__ uint32_t v_lo [B_ * CI_ * (N_ / 2)];

static __device__ __forceinline__ void hsplit(float v, uint16_t& h, uint16_t& l) {
    __half hb = __float2half(v);
    float hf = __half2float(hb);
    __half lb = __float2half(v - hf);
    h = __half_as_ushort(hb);
    l = __half_as_ushort(lb);
}
static __device__ __forceinline__ void bsplit(float v, uint16_t& h, uint16_t& l) {
    __nv_bfloat16 hb = __float2bfloat16(v);
    float hf = __bfloat162float(hb);
    __nv_bfloat16 lb = __float2bfloat16(v - hf);
    h = __bfloat16_as_ushort(hb);
    l = __bfloat16_as_ushort(lb);
}
static __device__ __forceinline__ float ex2f(float x) {
    float y; asm("ex2.approx.ftz.f32 %0, %1;" : "=f"(y) : "f"(x)); return y;
}
static __device__ __forceinline__ void mma_f16(
    float* c, const uint32_t* a, uint32_t b0, uint32_t b1)
{
    asm volatile(
        "mma.sync.aligned.m16n8k16.row.col.f32.f16.f16.f32 "
        "{%0,%1,%2,%3},{%4,%5,%6,%7},{%8,%9},{%0,%1,%2,%3};"
        : "+f"(c[0]), "+f"(c[1]), "+f"(c[2]), "+f"(c[3])
        : "r"(a[0]), "r"(a[1]), "r"(a[2]), "r"(a[3]), "r"(b0), "r"(b1));
}
static __device__ __forceinline__ void mma_bf16(
    float* c, const uint32_t* a, uint32_t b0, uint32_t b1)
{
    asm volatile(
        "mma.sync.aligned.m16n8k16.row.col.f32.bf16.bf16.f32 "
        "{%0,%1,%2,%3},{%4,%5,%6,%7},{%8,%9},{%0,%1,%2,%3};"
        : "+f"(c[0]), "+f"(c[1]), "+f"(c[2]), "+f"(c[3])
        : "r"(a[0]), "r"(a[1]), "r"(a[2]), "r"(a[3]), "r"(b0), "r"(b1));
}
static __device__ __forceinline__ uint32_t smem_u32(const void* p) {
    uint32_t a;
    asm("{ .reg .u64 t; cvta.to.shared.u64 t, %1; cvt.u32.u64 %0, t; }" : "=r"(a) : "l"(p));
    return a;
}
#define LDSM4(r, a) asm volatile( \
    "ldmatrix.sync.aligned.m8n8.x4.shared.b16 {%0,%1,%2,%3}, [%4];" \
    : "=r"((r)[0]), "=r"((r)[1]), "=r"((r)[2]), "=r"((r)[3]) : "r"(a))
#define CPA16(s, g)  asm volatile("cp.async.cg.shared.global [%0], [%1], 16;" :: "r"(s), "l"(g) : "memory")
#define CPA_COMMIT() asm volatile("cp.async.commit_group;" ::: "memory")
#define CPA_WAIT1()  asm volatile("cp.async.wait_group 1;" ::: "memory")
#define CPA_WAIT0()  asm volatile("cp.async.wait_group 0;" ::: "memory")

// ---------------------------------------------------------------------------
// Kernel 1: prep. Q/K -> fp16 hi/lo; V = g(x) -> bf16 hi/lo. 512 blocks.
// ---------------------------------------------------------------------------
__global__ __launch_bounds__(128) void prep_kernel(
    const float* __restrict__ x,
    const float* __restrict__ Wg,
    const float* __restrict__ bg)
{
    __shared__ __align__(16) float sW[CI_ * C_];
    __shared__ float sb[CI_];
    int tid = threadIdx.x;
    for (int i = tid; i < CI_ * C_; i += 128) sW[i] = Wg[i];
    if (tid < CI_) sb[tid] = bg[tid];
    __syncthreads();

    int gid = blockIdx.x * 128 + tid;          // 0 .. 4*B*N-1
    int quarter = gid >> 14;                   // uniform per block
    int idx = gid & (B_ * N_ - 1);
    int b = idx >> 12;
    int n = idx & (N_ - 1);
    const float* xp = x + (size_t)b * C_ * N_ + n;

    float xv[C_];
    #pragma unroll
    for (int c = 0; c < C_; c++) xv[c] = xp[c * N_];

    if (quarter == 0) {
        uint32_t rowbase = (uint32_t)idx * (C_ / 2);
        uint32_t msk = (n & 7) << 2;
        #pragma unroll
        for (int w = 0; w < C_ / 2; w++) {
            uint16_t h0, l0, h1, l1;
            hsplit(xv[2 * w + 0], h0, l0);
            hsplit(xv[2 * w + 1], h1, l1);
            qk_hi[rowbase + (w ^ msk)] = (uint32_t)h0 | ((uint32_t)h1 << 16);
            qk_lo[rowbase + (w ^ msk)] = (uint32_t)l0 | ((uint32_t)l1 << 16);
        }
    }

    int o0 = quarter * (CI_ / 4);
    #pragma unroll
    for (int o = 0; o < CI_ / 4; o++) {
        int oo = o0 + o;
        float acc = sb[oo];
        #pragma unroll
        for (int c4 = 0; c4 < C_; c4 += 4) {
            float4 w = *(const float4*)(sW + oo * C_ + c4);
            acc = fmaf(xv[c4 + 0], w.x, acc);
            acc = fmaf(xv[c4 + 1], w.y, acc);
            acc = fmaf(xv[c4 + 2], w.z, acc);
            acc = fmaf(xv[c4 + 3], w.w, acc);
        }
        uint16_t h, l;
        bsplit(acc, h, l);
        uint32_t widx = (uint32_t)(b * CI_ + oo) * (N_ / 2) + ((n >> 1) ^ ((oo & 7) << 2));
        uint32_t eidx = widx * 2 + (n & 1);
        ((uint16_t*)v_hi)[eidx] = h;
        ((uint16_t*)v_lo)[eidx] = l;
    }
}

// ---------------------------------------------------------------------------
// Kernel 2: HMMA flash. 8 warps = 2 key-groups x 4 m32 query-warps.
// Q frags in registers (fp16); 6-slot 3-pair cp.async ring, 1 sync/iter.
// QK fp16 3-product; PV: P bf16 single x V bf16 2-product.
// grid = 128 CTAs x 256 threads, 1 CTA/SM.
// ---------------------------------------------------------------------------
#define SLOTSZ 24576u        // KH +0, KL +8192, VH +16384, VL +20480
#define SWZo   147456u
#define SBZo   155648u
#define SM_TOTAL 155904u

__global__ __launch_bounds__(256, 1) void flash_mma(
    const float* __restrict__ x,
    const float* __restrict__ Wz,
    const float* __restrict__ bz,
    float* __restrict__ out)
{
    extern __shared__ char smem[];
    uint32_t sb32 = smem_u32(smem);
    int tid = threadIdx.x, wid = tid >> 5, lane = tid & 31;
    int g = lane >> 2, tig = lane & 3;
    int h  = wid >> 2;                  // key group: tiles 2s+h
    int wq = (wid & 3) * 32;            // query rows (m32)
    int b  = blockIdx.x >> 5;
    int q0 = (blockIdx.x & 31) * TQ;

    const uint4* gQKh = (const uint4*)(qk_hi + (size_t)b * N_ * (C_ / 2));
    const uint4* gQKl = (const uint4*)(qk_lo + (size_t)b * N_ * (C_ / 2));
    const uint4* gVh4 = (const uint4*)v_hi;
    const uint4* gVl4 = (const uint4*)v_lo;
    int bCI = b * CI_;

    // per-thread ldmatrix address components
    uint32_t sw   = (lane & 7) << 2;
    uint32_t r8   = (lane & 7) | ((lane >> 4) << 3);
    uint32_t m4   = ((lane >> 3) & 1) << 2;
    uint32_t qrow = lane & 15;
    uint32_t qm4  = (lane >> 4) << 2;

    // ---- epilogue constants ----
    for (int i = tid; i < C_ * CI_; i += 256) ((float*)(smem + SWZo))[i] = Wz[i];
    if (tid < C_) ((float*)(smem + SBZo))[tid] = bz[tid];

    // ---- stage Q (fp16) in slot region; LDSM m32 frags to registers ----
    uint32_t Qh[8][4], Ql[8][4];        // [ks*2+mt][frag]
    {
        const uint4* gh = gQKh + (size_t)q0 * 8;     // 128 rows x 8 uint4
        const uint4* gl = gQKl + (size_t)q0 * 8;
        uint4* sh = (uint4*)(smem);
        uint4* sl = (uint4*)(smem + 16384u);
        #pragma unroll
        for (int r = 0; r < 4; r++) { int i = r * 256 + tid; sh[i] = gh[i]; sl[i] = gl[i]; }
        __syncthreads();
        #pragma unroll
        for (int ks = 0; ks < 4; ks++)
            #pragma unroll
            for (int mt = 0; mt < 2; mt++) {
                uint32_t qa = sb32 + (uint32_t)(wq + mt * 16 + qrow) * 128
                            + ((((uint32_t)(ks * 8)) + qm4) ^ sw) * 4;
                LDSM4(Qh[ks * 2 + mt], qa);
                LDSM4(Ql[ks * 2 + mt], qa + 16384u);
            }
        __syncthreads();   // Q consumed before cp.async overwrites slots
    }

    // ---- prologue: issue pairs 0 and 1 (separate commit groups) ----
    #pragma unroll
    for (int p = 0; p < 2; p++) {
        #pragma unroll
        for (int hh = 0; hh < 2; hh++) {
            int kt = 2 * p + hh;
            uint32_t sl = sb32 + (uint32_t)((p % 3) * 2 + hh) * SLOTSZ;
            const uint4* gh = gQKh + (size_t)kt * 512;
            const uint4* gl = gQKl + (size_t)kt * 512;
            CPA16(sl + tid * 16,                 gh + tid);
            CPA16(sl + (tid + 256) * 16,         gh + tid + 256);
            CPA16(sl + 8192u + tid * 16,         gl + tid);
            CPA16(sl + 8192u + (tid + 256) * 16, gl + tid + 256);
            int o = tid >> 3, part = tid & 7;
            size_t s4 = (size_t)(bCI + o) * (N_ / 8) + (size_t)kt * 8 + part;
            CPA16(sl + 16384u + tid * 16, gVh4 + s4);
            CPA16(sl + 20480u + tid * 16, gVl4 + s4);
        }
        CPA_COMMIT();
    }

    float Y[2][4][4];
    #pragma unroll
    for (int mt = 0; mt < 2; mt++)
        #pragma unroll
        for (int ot = 0; ot < 4; ot++)
            #pragma unroll
            for (int r = 0; r < 4; r++) Y[mt][ot][r] = 0.f;
    float l4[4] = {0.f, 0.f, 0.f, 0.f};

    for (int s = 0; s < NPAIR; s++) {
        if (s < NPAIR - 1) { CPA_WAIT1(); } else { CPA_WAIT0(); }
        __syncthreads();    // pair s visible to all; all reads of slot (s+2)%3 done

        // issue pair s+2 into ring slot (s+2)%3
        if (s + 2 < NPAIR) {
            int p = (s + 2) % 3;
            #pragma unroll
            for (int hh = 0; hh < 2; hh++) {
                int kt = 2 * (s + 2) + hh;
                uint32_t sl = sb32 + (uint32_t)(p * 2 + hh) * SLOTSZ;
                const uint4* gh = gQKh + (size_t)kt * 512;
                const uint4* gl = gQKl + (size_t)kt * 512;
                CPA16(sl + tid * 16,                 gh + tid);
                CPA16(sl + (tid + 256) * 16,         gh + tid + 256);
                CPA16(sl + 8192u + tid * 16,         gl + tid);
                CPA16(sl + 8192u + (tid + 256) * 16, gl + tid + 256);
                int o = tid >> 3, part = tid & 7;
                size_t s4 = (size_t)(bCI + o) * (N_ / 8) + (size_t)kt * 8 + part;
                CPA16(sl + 16384u + tid * 16, gVh4 + s4);
                CPA16(sl + 20480u + tid * 16, gVl4 + s4);
            }
            CPA_COMMIT();
        }

        uint32_t slotb = sb32 + (uint32_t)((s % 3) * 2 + h) * SLOTSZ;

        // ---- two n32 key-halves ----
        #pragma unroll
        for (int half = 0; half < 2; half++) {
            // ===== QK^T (m32 x n32) =====
            float S[2][4][4];
            #pragma unroll
            for (int mt = 0; mt < 2; mt++)
                #pragma unroll
                for (int nt = 0; nt < 4; nt++)
                    #pragma unroll
                    for (int r = 0; r < 4; r++) S[mt][nt][r] = 0.f;

            #pragma unroll
            for (int ks = 0; ks < 4; ks++) {
                uint32_t kw = ((uint32_t)(ks * 8) + m4) ^ sw;
                #pragma unroll
                for (int ntp = 0; ntp < 2; ntp++) {
                    uint32_t ka = slotb + (uint32_t)(half * 32 + ntp * 16 + r8) * 128 + kw * 4;
                    uint32_t kh[4], kl[4];
                    LDSM4(kh, ka);
                    LDSM4(kl, ka + 8192u);
                    #pragma unroll
                    for (int mt = 0; mt < 2; mt++) {
                        mma_f16(S[mt][2 * ntp + 0], Qh[ks * 2 + mt], kh[0], kh[1]);
                        mma_f16(S[mt][2 * ntp + 0], Qh[ks * 2 + mt], kl[0], kl[1]);
                        mma_f16(S[mt][2 * ntp + 0], Ql[ks * 2 + mt], kh[0], kh[1]);
                        mma_f16(S[mt][2 * ntp + 1], Qh[ks * 2 + mt], kh[2], kh[3]);
                        mma_f16(S[mt][2 * ntp + 1], Qh[ks * 2 + mt], kl[2], kl[3]);
                        mma_f16(S[mt][2 * ntp + 1], Ql[ks * 2 + mt], kh[2], kh[3]);
                    }
                }
            }

            // ===== softmax (fixed basis, P single bf16) + PV (V 2-product) =====
            #pragma unroll
            for (int js2 = 0; js2 < 2; js2++) {
                uint32_t P[2][4];
                #pragma unroll
                for (int mt = 0; mt < 2; mt++)
                    #pragma unroll
                    for (int hn = 0; hn < 2; hn++) {
                        const float* sv = S[mt][2 * js2 + hn];
                        #pragma unroll
                        for (int rh = 0; rh < 2; rh++) {
                            float p0 = ex2f(fmaf(sv[2 * rh + 0], LOG2E, -M0L2));
                            float p1 = ex2f(fmaf(sv[2 * rh + 1], LOG2E, -M0L2));
                            __nv_bfloat162 H = __floats2bfloat162_rn(p0, p1);
                            // accumulate l from the ROUNDED weights (consistency)
                            l4[mt * 2 + rh] += __bfloat162float(H.x) + __bfloat162float(H.y);
                            P[mt][hn * 2 + rh] = *(uint32_t*)&H;
                        }
                    }
                uint32_t vw = ((uint32_t)((half * 2 + js2) * 8) + m4) ^ sw;
                #pragma unroll
                for (int otp = 0; otp < 2; otp++) {
                    uint32_t va = slotb + 16384u + (uint32_t)(otp * 16 + r8) * 128 + vw * 4;
                    uint32_t vh[4], vl[4];
                    LDSM4(vh, va);
                    LDSM4(vl, va + 4096u);
                    #pragma unroll
                    for (int mt = 0; mt < 2; mt++) {
                        mma_bf16(Y[mt][2 * otp + 0], P[mt], vh[0], vh[1]);
                        mma_bf16(Y[mt][2 * otp + 0], P[mt], vl[0], vl[1]);
                        mma_bf16(Y[mt][2 * otp + 1], P[mt], vh[2], vh[3]);
                        mma_bf16(Y[mt][2 * otp + 1], P[mt], vl[2], vl[3]);
                    }
                }
            }
        }
    }

    // ---- reduce l across tig; stage group partials in slot region ----
    #pragma unroll
    for (int k = 0; k < 4; k++) {
        l4[k] += __shfl_xor_sync(0xffffffffu, l4[k], 1);
        l4[k] += __shfl_xor_sync(0xffffffffu, l4[k], 2);
    }
    __syncthreads();                     // all slot reads done
    float* sY  = (float*)(smem);         // 2 groups x 128q x 32o = 32KB
    float* sLp = (float*)(smem + 32768u);
    if (tig == 0) {
        #pragma unroll
        for (int mt = 0; mt < 2; mt++) {
            sLp[h * 128 + wq + mt * 16 + g]     = l4[2 * mt + 0];
            sLp[h * 128 + wq + mt * 16 + g + 8] = l4[2 * mt + 1];
        }
    }
    #pragma unroll
    for (int mt = 0; mt < 2; mt++) {
        int r0 = h * 128 + wq + mt * 16 + g;
        #pragma unroll
        for (int ot = 0; ot < 4; ot++) {
            int oc = ot * 8 + 2 * tig;
            *(float2*)(sY + (r0)     * 32 + oc) = make_float2(Y[mt][ot][0], Y[mt][ot][1]);
            *(float2*)(sY + (r0 + 8) * 32 + oc) = make_float2(Y[mt][ot][2], Y[mt][ot][3]);
        }
    }
    __syncthreads();

    // ---- epilogue: combine groups; 2 threads per query ----
    {
        int q  = tid & 127;
        int ch = tid >> 7;
        float rinv = 1.f / (sLp[q] + sLp[128 + q]);
        float y[CI_];
        #pragma unroll
        for (int o4 = 0; o4 < CI_; o4 += 4) {
            float4 a = *(const float4*)(sY + q * 32 + o4);
            float4 c = *(const float4*)(sY + (128 + q) * 32 + o4);
            y[o4 + 0] = (a.x + c.x) * rinv;
            y[o4 + 1] = (a.y + c.y) * rinv;
            y[o4 + 2] = (a.z + c.z) * rinv;
            y[o4 + 3] = (a.w + c.w) * rinv;
        }

        const float* sWZ = (const float*)(smem + SWZo);
        const float* sBZ = (const float*)(smem + SBZo);
        const float* xb = x + (size_t)b * C_ * N_;
        int qg = q0 + q;
        #pragma unroll
        for (int cc = 0; cc < 32; cc++) {
            int c = ch * 32 + cc;
            float acc = sBZ[c];
            #pragma unroll
            for (int o4 = 0; o4 < CI_; o4 += 4) {
                float4 w = *(const float4*)(sWZ + c * CI_ + o4);
                acc = fmaf(w.x, y[o4 + 0], acc);
                acc = fmaf(w.y, y[o4 + 1], acc);
                acc = fmaf(w.z, y[o4 + 2], acc);
                acc = fmaf(w.w, y[o4 + 3], acc);
            }
            out[((size_t)b * C_ + c) * N_ + qg] = acc + xb[c * N_ + qg];
        }
    }
}

// ---------------------------------------------------------------------------
extern "C" void kernel_launch(void* const* d_in, const int* in_sizes, int n_in,
                              void* d_out, int out_size)
{
    const float* x  = (const float*)d_in[0];
    const float* Wg = (const float*)d_in[1];
    const float* bg = (const float*)d_in[2];
    const float* Wz = (const float*)d_in[3];
    const float* bz = (const float*)d_in[4];
    float* out = (float*)d_out;

    cudaFuncSetAttribute(flash_mma, cudaFuncAttributeMaxDynamicSharedMemorySize, SM_TOTAL);

    prep_kernel<<<(4 * B_ * N_) / 128, 128>>>(x, Wg, bg);
    flash_mma<<<B_ * (N_ / TQ), 256, SM_TOTAL>>>(x, Wz, bz, out);
}